// round 5
// baseline (speedup 1.0000x reference)
#include <cuda_runtime.h>
#include <cuda_bf16.h>
#include <math.h>
#include <stdint.h>

#define N_TOT 8192
#define F_DIM 128
#define TBLK  64                 // 8192 / 128
#define NTILES (TBLK*(TBLK+1)/2) // 2080 upper-triangle tiles
#define ROWB  272                // padded smem row bytes (128 bf16 + 8 pad)
#define SM_TILE (128 * ROWB)     // 34816 bytes per tile
#define SM_TOTAL (2 * SM_TILE)   // 69632

// Device scratch (allocation-free rules)
__device__ __nv_bfloat16 g_xb[N_TOT * F_DIM];   // scaled normalized feats [N][F] bf16
__device__ float g_part[NTILES];
__device__ unsigned int g_count = 0;

__device__ __forceinline__ uint32_t smem_u32(const void* p) {
    uint32_t a;
    asm("{ .reg .u64 t; cvta.to.shared.u64 t, %1; cvt.u32.u64 %0, t; }" : "=r"(a) : "l"(p));
    return a;
}
__device__ __forceinline__ float ex2a(float x) {
    float y; asm("ex2.approx.f32 %0, %1;" : "=f"(y) : "f"(x)); return y;
}

// ---------------------------------------------------------------------------
// Kernel 1: normalize + fold sqrt(10/ln2) + bf16 convert. 16 rows per block.
// x layout (B=8, F=128, THW=1024), n = b*1024 + thw (thw0 multiple of 16).
// ---------------------------------------------------------------------------
__global__ void __launch_bounds__(256) normalize_kernel(const float* __restrict__ x) {
    __shared__ float sm[16 * 130];
    __shared__ float ssp[16][17];
    __shared__ float rn[16];

    const int tid = threadIdx.x;
    const int n0  = blockIdx.x * 16;
    const int b   = n0 >> 10;
    const int thw0 = n0 & 1023;
    const float* base = x + (size_t)b * 131072 + thw0;

    // load 128 f x 16 n as float4 along n; scatter-store transposed
#pragma unroll
    for (int it = 0; it < 2; ++it) {
        int idx = it * 256 + tid;
        int q = idx & 3;          // float4 index along n
        int f = idx >> 2;         // 0..127
        float4 v = *(const float4*)&base[(size_t)f * 1024 + q * 4];
        sm[(q * 4 + 0) * 130 + f] = v.x;
        sm[(q * 4 + 1) * 130 + f] = v.y;
        sm[(q * 4 + 2) * 130 + f] = v.z;
        sm[(q * 4 + 3) * 130 + f] = v.w;
    }
    __syncthreads();

    {
        int r = tid & 15, part = tid >> 4;
        float ss = 0.f;
#pragma unroll
        for (int f = part * 8; f < part * 8 + 8; ++f) {
            float v = sm[r * 130 + f];
            ss += v * v;
        }
        ssp[part][r] = ss;
    }
    __syncthreads();
    if (tid < 16) {
        float ss = 0.f;
#pragma unroll
        for (int p = 0; p < 16; ++p) ss += ssp[p][tid];
        // 3.7982825 = sqrt(10 / ln 2); folds exp scale into the data
        rn[tid] = (1.0f / fmaxf(sqrtf(ss), 1e-12f)) * 3.7982825f;
    }
    __syncthreads();

    uint32_t* out = (uint32_t*)(g_xb + (size_t)n0 * F_DIM);
#pragma unroll
    for (int it = 0; it < 4; ++it) {
        int idx = it * 256 + tid;
        int f2 = idx & 63;
        int r  = idx >> 6;
        float s = rn[r];
        float2 v = *(const float2*)&sm[r * 130 + f2 * 2];
        __nv_bfloat162 h = __floats2bfloat162_rn(v.x * s, v.y * s);
        out[r * 64 + f2] = *(uint32_t*)&h;
    }
}

// ---------------------------------------------------------------------------
// Kernel 2: HMMA bf16 128x128x128 tile + fused exp-sum + last-block finalize.
// No min-blocks cap (R4 lesson: 128-reg cap spills the 64 accumulators).
// ---------------------------------------------------------------------------
__global__ void __launch_bounds__(256) simexp_kernel(float* __restrict__ out) {
    extern __shared__ char smem[];
    const uint32_t sbase = smem_u32(smem);
    const int tid  = threadIdx.x;
    const int wid  = tid >> 5;
    const int lane = tid & 31;

    // linear tile id -> (bi, bj), bj >= bi
    int t = blockIdx.x;
    int bi = (int)((129.0f - sqrtf(16641.0f - 8.0f * (float)t)) * 0.5f);
    while ((bi + 1) * (129 - (bi + 1)) / 2 <= t) ++bi;
    while (bi * (129 - bi) / 2 > t) --bi;
    const int bj = bi + (t - bi * (129 - bi) / 2);
    const bool diag = (bi == bj);

    // cooperative tile loads (LDG + STS)
    {
        const uint4* gA = (const uint4*)(g_xb + (size_t)bi * 128 * F_DIM);
#pragma unroll
        for (int it = 0; it < 8; ++it) {
            int idx = it * 256 + tid;
            int r = idx >> 4, q = idx & 15;
            *(uint4*)(smem + r * ROWB + q * 16) = gA[idx];
        }
        if (!diag) {
            const uint4* gB = (const uint4*)(g_xb + (size_t)bj * 128 * F_DIM);
#pragma unroll
            for (int it = 0; it < 8; ++it) {
                int idx = it * 256 + tid;
                int r = idx >> 4, q = idx & 15;
                *(uint4*)(smem + SM_TILE + r * ROWB + q * 16) = gB[idx];
            }
        }
    }
    __syncthreads();

    const uint32_t aBase = sbase;
    const uint32_t bBase = diag ? sbase : (sbase + SM_TILE);

    const int wm = (wid >> 2) * 64;
    const int wn = (wid & 3) * 32;
    const int g  = lane >> 3;
    const int lr = lane & 7;

    float acc[4][4][4];
#pragma unroll
    for (int mt = 0; mt < 4; ++mt)
#pragma unroll
        for (int nt = 0; nt < 4; ++nt)
#pragma unroll
            for (int c = 0; c < 4; ++c) acc[mt][nt][c] = 0.f;

#pragma unroll
    for (int kc = 0; kc < 8; ++kc) {
        uint32_t a[4][4];
#pragma unroll
        for (int mt = 0; mt < 4; ++mt) {
            int row = wm + mt * 16 + (g & 1) * 8 + lr;
            uint32_t addr = aBase + row * ROWB + kc * 32 + (g >> 1) * 16;
            asm volatile("ldmatrix.sync.aligned.m8n8.x4.shared.b16 {%0,%1,%2,%3}, [%4];"
                         : "=r"(a[mt][0]), "=r"(a[mt][1]), "=r"(a[mt][2]), "=r"(a[mt][3])
                         : "r"(addr));
        }
        uint32_t bf[2][4];
#pragma unroll
        for (int np = 0; np < 2; ++np) {
            int row = wn + np * 16 + (g >> 1) * 8 + lr;
            uint32_t addr = bBase + row * ROWB + kc * 32 + (g & 1) * 16;
            asm volatile("ldmatrix.sync.aligned.m8n8.x4.shared.b16 {%0,%1,%2,%3}, [%4];"
                         : "=r"(bf[np][0]), "=r"(bf[np][1]), "=r"(bf[np][2]), "=r"(bf[np][3])
                         : "r"(addr));
        }
#pragma unroll
        for (int mt = 0; mt < 4; ++mt)
#pragma unroll
            for (int nt = 0; nt < 4; ++nt) {
                uint32_t b0 = bf[nt >> 1][(nt & 1) * 2];
                uint32_t b1 = bf[nt >> 1][(nt & 1) * 2 + 1];
                asm volatile(
                    "mma.sync.aligned.m16n8k16.row.col.f32.bf16.bf16.f32 "
                    "{%0,%1,%2,%3}, {%4,%5,%6,%7}, {%8,%9}, {%0,%1,%2,%3};"
                    : "+f"(acc[mt][nt][0]), "+f"(acc[mt][nt][1]),
                      "+f"(acc[mt][nt][2]), "+f"(acc[mt][nt][3])
                    : "r"(a[mt][0]), "r"(a[mt][1]), "r"(a[mt][2]), "r"(a[mt][3]),
                      "r"(b0), "r"(b1));
            }
    }

    // epilogue: scale pre-folded -> bare 2^acc; skip i==j on diag tiles
    const int lrow = lane >> 2;
    const int lcol = (lane & 3) * 2;
    float s0 = 0.f, s1 = 0.f;
#pragma unroll
    for (int mt = 0; mt < 4; ++mt)
#pragma unroll
        for (int nt = 0; nt < 4; ++nt)
#pragma unroll
            for (int c = 0; c < 4; ++c) {
                int r_ = wm + mt * 16 + ((c >> 1) << 3) + lrow;
                int c_ = wn + nt * 8 + lcol + (c & 1);
                if (diag && r_ == c_) continue;
                if (c & 1) s1 += ex2a(acc[mt][nt][c]);
                else       s0 += ex2a(acc[mt][nt][c]);
            }
    float s = s0 + s1;
    if (!diag) s *= 2.f;

    __shared__ float red[8];
#pragma unroll
    for (int off = 16; off > 0; off >>= 1)
        s += __shfl_down_sync(0xFFFFFFFFu, s, off);
    if (lane == 0) red[wid] = s;
    __syncthreads();

    __shared__ bool isLast;
    if (tid == 0) {
        float tsum = 0.f;
#pragma unroll
        for (int w = 0; w < 8; ++w) tsum += red[w];
        g_part[blockIdx.x] = tsum;
        __threadfence();
        unsigned int c = atomicAdd(&g_count, 1u);
        isLast = (c == NTILES - 1);
    }
    __syncthreads();

    // deterministic final reduction by the last block (fixed summation order)
    if (isLast) {
        float fs = 0.f;
        for (int i = tid; i < NTILES; i += 256) fs += __ldcg(&g_part[i]);
#pragma unroll
        for (int off = 16; off > 0; off >>= 1)
            fs += __shfl_down_sync(0xFFFFFFFFu, fs, off);
        if (lane == 0) red[wid] = fs;
        __syncthreads();
        if (tid == 0) {
            float tot = 0.f;
#pragma unroll
            for (int w = 0; w < 8; ++w) tot += red[w];
            out[0] = logf(tot);
            g_count = 0;   // reset for next (graph-replayed) launch
        }
    }
}

extern "C" void kernel_launch(void* const* d_in, const int* in_sizes, int n_in,
                              void* d_out, int out_size) {
    const float* x = (const float*)d_in[0];
    float* out = (float*)d_out;
    (void)in_sizes; (void)n_in; (void)out_size;

    cudaFuncSetAttribute(simexp_kernel, cudaFuncAttributeMaxDynamicSharedMemorySize, SM_TOTAL);

    normalize_kernel<<<N_TOT / 16, 256>>>(x);
    simexp_kernel<<<NTILES, 256, SM_TOTAL>>>(out);
}

// round 6
// speedup vs baseline: 1.2222x; 1.2222x over previous
#include <cuda_runtime.h>
#include <cuda_bf16.h>
#include <math.h>
#include <stdint.h>

#define N_TOT 8192
#define F_DIM 128
#define TBLK  64                 // 8192 / 128
#define NTILES (TBLK*(TBLK+1)/2) // 2080 upper-triangle tiles
#define ROWB  272                // padded smem row bytes (128 bf16 + 8 pad)
#define SM_TILE (128 * ROWB)     // 34816 bytes per tile
#define SM_TOTAL (2 * SM_TILE)   // 69632

// Device scratch (allocation-free rules)
__device__ __nv_bfloat16 g_xb[N_TOT * F_DIM];   // normalized feats [N][F] bf16
__device__ float g_part[NTILES];

__device__ __forceinline__ uint32_t smem_u32(const void* p) {
    uint32_t a;
    asm("{ .reg .u64 t; cvta.to.shared.u64 t, %1; cvt.u32.u64 %0, t; }" : "=r"(a) : "l"(p));
    return a;
}
__device__ __forceinline__ float ex2a(float x) {
    float y; asm("ex2.approx.f32 %0, %1;" : "=f"(y) : "f"(x)); return y;
}

// ---------------------------------------------------------------------------
// Kernel 1: normalize + bf16 convert. 16 rows per block (fast R4 version,
// WITHOUT the scale fold — keeps simexp identical to the proven R3 kernel).
// ---------------------------------------------------------------------------
__global__ void __launch_bounds__(256) normalize_kernel(const float* __restrict__ x) {
    __shared__ float sm[16 * 130];
    __shared__ float ssp[16][17];
    __shared__ float rn[16];

    const int tid = threadIdx.x;
    const int n0  = blockIdx.x * 16;
    const int b   = n0 >> 10;
    const int thw0 = n0 & 1023;
    const float* base = x + (size_t)b * 131072 + thw0;

#pragma unroll
    for (int it = 0; it < 2; ++it) {
        int idx = it * 256 + tid;
        int q = idx & 3;
        int f = idx >> 2;
        float4 v = *(const float4*)&base[(size_t)f * 1024 + q * 4];
        sm[(q * 4 + 0) * 130 + f] = v.x;
        sm[(q * 4 + 1) * 130 + f] = v.y;
        sm[(q * 4 + 2) * 130 + f] = v.z;
        sm[(q * 4 + 3) * 130 + f] = v.w;
    }
    __syncthreads();

    {
        int r = tid & 15, part = tid >> 4;
        float ss = 0.f;
#pragma unroll
        for (int f = part * 8; f < part * 8 + 8; ++f) {
            float v = sm[r * 130 + f];
            ss += v * v;
        }
        ssp[part][r] = ss;
    }
    __syncthreads();
    if (tid < 16) {
        float ss = 0.f;
#pragma unroll
        for (int p = 0; p < 16; ++p) ss += ssp[p][tid];
        rn[tid] = 1.0f / fmaxf(sqrtf(ss), 1e-12f);
    }
    __syncthreads();

    uint32_t* out = (uint32_t*)(g_xb + (size_t)n0 * F_DIM);
#pragma unroll
    for (int it = 0; it < 4; ++it) {
        int idx = it * 256 + tid;
        int f2 = idx & 63;
        int r  = idx >> 6;
        float s = rn[r];
        float2 v = *(const float2*)&sm[r * 130 + f2 * 2];
        __nv_bfloat162 h = __floats2bfloat162_rn(v.x * s, v.y * s);
        out[r * 64 + f2] = *(uint32_t*)&h;
    }
}

// ---------------------------------------------------------------------------
// Kernel 2: HMMA (mma.sync bf16) 128x128x128 tile + fused exp-sum epilogue.
// Verbatim the R3 version that measured ~29us.
// ---------------------------------------------------------------------------
__global__ void __launch_bounds__(256) simexp_kernel() {
    extern __shared__ char smem[];
    const int tid  = threadIdx.x;
    const int wid  = tid >> 5;
    const int lane = tid & 31;

    // linear tile id -> (bi, bj), bj >= bi; start(bi) = bi*(129-bi)/2
    int t = blockIdx.x;
    int bi = (int)((129.0f - sqrtf(16641.0f - 8.0f * (float)t)) * 0.5f);
    while ((bi + 1) * (129 - (bi + 1)) / 2 <= t) ++bi;
    while (bi * (129 - bi) / 2 > t) --bi;
    const int bj = bi + (t - bi * (129 - bi) / 2);
    const bool diag = (bi == bj);

    // --- cooperative tile loads: 128 rows x 256B, padded rows of 272B ---
    {
        const uint4* gA = (const uint4*)(g_xb + (size_t)bi * 128 * F_DIM);
#pragma unroll
        for (int it = 0; it < 8; ++it) {
            int idx = it * 256 + tid;
            int r = idx >> 4, q = idx & 15;
            *(uint4*)(smem + r * ROWB + q * 16) = gA[idx];
        }
        if (!diag) {
            const uint4* gB = (const uint4*)(g_xb + (size_t)bj * 128 * F_DIM);
#pragma unroll
            for (int it = 0; it < 8; ++it) {
                int idx = it * 256 + tid;
                int r = idx >> 4, q = idx & 15;
                *(uint4*)(smem + SM_TILE + r * ROWB + q * 16) = gB[idx];
            }
        }
    }
    __syncthreads();

    const uint32_t aBase = smem_u32(smem);
    const uint32_t bBase = diag ? aBase : (aBase + SM_TILE);

    const int wm = (wid >> 2) * 64;   // warp m offset
    const int wn = (wid & 3) * 32;    // warp n offset
    const int g  = lane >> 3;         // ldmatrix quad group
    const int lr = lane & 7;

    float acc[4][4][4];
#pragma unroll
    for (int mt = 0; mt < 4; ++mt)
#pragma unroll
        for (int nt = 0; nt < 4; ++nt)
#pragma unroll
            for (int c = 0; c < 4; ++c) acc[mt][nt][c] = 0.f;

#pragma unroll
    for (int kc = 0; kc < 8; ++kc) {
        // A fragments: 4 m-tiles of 16x16
        uint32_t a[4][4];
#pragma unroll
        for (int mt = 0; mt < 4; ++mt) {
            int row = wm + mt * 16 + (g & 1) * 8 + lr;
            uint32_t addr = aBase + row * ROWB + kc * 32 + (g >> 1) * 16;
            asm volatile("ldmatrix.sync.aligned.m8n8.x4.shared.b16 {%0,%1,%2,%3}, [%4];"
                         : "=r"(a[mt][0]), "=r"(a[mt][1]), "=r"(a[mt][2]), "=r"(a[mt][3])
                         : "r"(addr));
        }
        // B fragments: 2 x ldmatrix.x4, each covers two n8 frags
        uint32_t bf[2][4];
#pragma unroll
        for (int np = 0; np < 2; ++np) {
            int row = wn + np * 16 + (g >> 1) * 8 + lr;
            uint32_t addr = bBase + row * ROWB + kc * 32 + (g & 1) * 16;
            asm volatile("ldmatrix.sync.aligned.m8n8.x4.shared.b16 {%0,%1,%2,%3}, [%4];"
                         : "=r"(bf[np][0]), "=r"(bf[np][1]), "=r"(bf[np][2]), "=r"(bf[np][3])
                         : "r"(addr));
        }
#pragma unroll
        for (int mt = 0; mt < 4; ++mt)
#pragma unroll
            for (int nt = 0; nt < 4; ++nt) {
                uint32_t b0 = bf[nt >> 1][(nt & 1) * 2];
                uint32_t b1 = bf[nt >> 1][(nt & 1) * 2 + 1];
                asm volatile(
                    "mma.sync.aligned.m16n8k16.row.col.f32.bf16.bf16.f32 "
                    "{%0,%1,%2,%3}, {%4,%5,%6,%7}, {%8,%9}, {%0,%1,%2,%3};"
                    : "+f"(acc[mt][nt][0]), "+f"(acc[mt][nt][1]),
                      "+f"(acc[mt][nt][2]), "+f"(acc[mt][nt][3])
                    : "r"(a[mt][0]), "r"(a[mt][1]), "r"(a[mt][2]), "r"(a[mt][3]),
                      "r"(b0), "r"(b1));
            }
    }

    // --- epilogue: exp(sim * 10) and sum, skipping i==j on diag tiles ---
    const int lrow = lane >> 2;
    const int lcol = (lane & 3) * 2;
    const float SC = 14.4269504088896f;   // 10 / ln(2)
    float s = 0.f;
#pragma unroll
    for (int mt = 0; mt < 4; ++mt)
#pragma unroll
        for (int nt = 0; nt < 4; ++nt)
#pragma unroll
            for (int c = 0; c < 4; ++c) {
                int r_ = wm + mt * 16 + ((c >> 1) << 3) + lrow;
                int c_ = wn + nt * 8 + lcol + (c & 1);
                if (diag && r_ == c_) continue;
                s += ex2a(acc[mt][nt][c] * SC);
            }
    if (!diag) s *= 2.f;

    __shared__ float red[8];
#pragma unroll
    for (int off = 16; off > 0; off >>= 1)
        s += __shfl_down_sync(0xFFFFFFFFu, s, off);
    if (lane == 0) red[wid] = s;
    __syncthreads();
    if (tid == 0) {
        float tsum = 0.f;
#pragma unroll
        for (int w = 0; w < 8; ++w) tsum += red[w];
        g_part[blockIdx.x] = tsum;
    }
}

// ---------------------------------------------------------------------------
// Kernel 3: deterministic final reduction + log
// ---------------------------------------------------------------------------
__global__ void __launch_bounds__(256) finalize_kernel(float* __restrict__ out) {
    __shared__ float red[8];
    float s = 0.f;
    for (int i = threadIdx.x; i < NTILES; i += 256) s += g_part[i];
#pragma unroll
    for (int off = 16; off > 0; off >>= 1)
        s += __shfl_down_sync(0xFFFFFFFFu, s, off);
    if ((threadIdx.x & 31) == 0) red[threadIdx.x >> 5] = s;
    __syncthreads();
    if (threadIdx.x == 0) {
        float tsum = 0.f;
#pragma unroll
        for (int w = 0; w < 8; ++w) tsum += red[w];
        out[0] = logf(tsum);
    }
}

extern "C" void kernel_launch(void* const* d_in, const int* in_sizes, int n_in,
                              void* d_out, int out_size) {
    const float* x = (const float*)d_in[0];
    float* out = (float*)d_out;
    (void)in_sizes; (void)n_in; (void)out_size;

    cudaFuncSetAttribute(simexp_kernel, cudaFuncAttributeMaxDynamicSharedMemorySize, SM_TOTAL);

    normalize_kernel<<<N_TOT / 16, 256>>>(x);
    simexp_kernel<<<NTILES, 256, SM_TOTAL>>>();
    finalize_kernel<<<1, 256>>>(out);
}